// round 1
// baseline (speedup 1.0000x reference)
#include <cuda_runtime.h>
#include <math.h>

#define TB 4
#define TT 1024
#define TC 1024
#define TH 16
#define THD 64
#define MR (TB*TT)          // 4096 rows
#define N3C (3*TC)          // 3072

// Scratch (allocation-free rule: device globals)
static __device__ float g_qkv[(size_t)MR * N3C];   // 48 MB
static __device__ float g_yatt[(size_t)MR * TC];   // 16 MB

// ---------------------------------------------------------------------------
// SGEMM: C[M,N] = A[M,K] @ B[K,N], all row-major. 128x128 tile, BK=8,
// 256 threads, 8x8 register tile per thread.
// ---------------------------------------------------------------------------
__global__ __launch_bounds__(256) void sgemm128(const float* __restrict__ A,
                                                const float* __restrict__ B,
                                                float* __restrict__ C,
                                                int M, int N, int K)
{
    __shared__ float As[8][128];
    __shared__ float Bs[8][128];
    const int t  = threadIdx.x;
    const int tx = t & 15;
    const int ty = t >> 4;
    const int arow = t >> 1;
    const int acol = (t & 1) << 2;
    const int brow = t >> 5;
    const int bcol = (t & 31) << 2;
    const float* Ab = A + (size_t)(blockIdx.y * 128) * K;
    const float* Bb = B + blockIdx.x * 128;

    float acc[8][8];
    #pragma unroll
    for (int i = 0; i < 8; i++)
        #pragma unroll
        for (int j = 0; j < 8; j++) acc[i][j] = 0.f;

    for (int k0 = 0; k0 < K; k0 += 8) {
        float4 av = *(const float4*)(Ab + (size_t)arow * K + k0 + acol);
        float4 bv = *(const float4*)(Bb + (size_t)(k0 + brow) * N + bcol);
        As[acol+0][arow] = av.x;
        As[acol+1][arow] = av.y;
        As[acol+2][arow] = av.z;
        As[acol+3][arow] = av.w;
        *(float4*)(&Bs[brow][bcol]) = bv;
        __syncthreads();
        #pragma unroll
        for (int kk = 0; kk < 8; kk++) {
            float ar[8], br[8];
            *(float4*)(ar)     = *(const float4*)(&As[kk][ty*8]);
            *(float4*)(ar + 4) = *(const float4*)(&As[kk][ty*8 + 4]);
            *(float4*)(br)     = *(const float4*)(&Bs[kk][tx*8]);
            *(float4*)(br + 4) = *(const float4*)(&Bs[kk][tx*8 + 4]);
            #pragma unroll
            for (int i = 0; i < 8; i++)
                #pragma unroll
                for (int j = 0; j < 8; j++)
                    acc[i][j] = fmaf(ar[i], br[j], acc[i][j]);
        }
        __syncthreads();
    }

    float* Cb = C + (size_t)(blockIdx.y*128 + ty*8) * N + blockIdx.x*128 + tx*8;
    #pragma unroll
    for (int i = 0; i < 8; i++) {
        *(float4*)(Cb + (size_t)i * N)     = make_float4(acc[i][0], acc[i][1], acc[i][2], acc[i][3]);
        *(float4*)(Cb + (size_t)i * N + 4) = make_float4(acc[i][4], acc[i][5], acc[i][6], acc[i][7]);
    }
}

// ---------------------------------------------------------------------------
// Fused masked attention. One CTA per (query-tile of 64, head, batch).
// Streams key tiles of 64; since wexp >= 0 and magnitudes are tiny
// (|logit| ~ O(1)), no running max is needed — exp matches reference exactly.
// Per-head span cutoff lets us skip key tiles whose mask is identically 0.
//
// smem layouts (all 64x64 fp32, conflict-free float4/broadcast access):
//   Qt[d][q], Kt[d][k]  (d-major for the S outer-product GEMM)
//   Vs[k][d], Pt[k][q]
// Thread map (16x16): S tile: (ty->k, tx->q); PV tile: (ty->q, tx->d).
// ---------------------------------------------------------------------------
__global__ __launch_bounds__(256) void attn_kernel(const float* __restrict__ qkv,
                                                   const float* __restrict__ span_params,
                                                   const float* __restrict__ stride_params,
                                                   float* __restrict__ yatt)
{
    extern __shared__ float sm[];
    float* Qt   = sm;            // 4096
    float* Kt   = sm + 4096;     // 4096
    float* Vs   = sm + 8192;     // 4096
    float* Pt   = sm + 12288;    // 4096
    float* lred = sm + 16384;    // 64

    const int qt = blockIdx.x, h = blockIdx.y, b = blockIdx.z;
    const int t  = threadIdx.x;
    const int tx = t & 15, ty = t >> 4;
    const int i0 = qt * 64;

    // head parameters (cheap, recomputed per block)
    const float sp = 1024.f / (1.f + __expf(-span_params[h]));
    const float p0 = stride_params[2*h], p1 = stride_params[2*h + 1];
    const float mxp = fmaxf(p0, p1);
    const float e0 = __expf(p0 - mxp), e1 = __expf(p1 - mxp);
    const float sw0 = e0 / (e0 + e1), sw1 = e1 / (e0 + e1);

    const float* base = qkv + (size_t)b * TT * N3C + h * THD;

    const int lr  = t >> 2;        // row within 64-tile this thread loads
    const int ld0 = (t & 3) << 4;  // starting d (16 floats per thread)

    // Load Q tile transposed into Qt[d][q]
    {
        const float* src = base + (size_t)(i0 + lr) * N3C + ld0;
        #pragma unroll
        for (int i = 0; i < 16; i += 4) {
            float4 v = *(const float4*)(src + i);
            Qt[(ld0+i+0)*64 + lr] = v.x;
            Qt[(ld0+i+1)*64 + lr] = v.y;
            Qt[(ld0+i+2)*64 + lr] = v.z;
            Qt[(ld0+i+3)*64 + lr] = v.w;
        }
    }
    if (t < 64) lred[t] = 0.f;

    float accy[4][4] = {{0.f,0.f,0.f,0.f},{0.f,0.f,0.f,0.f},
                        {0.f,0.f,0.f,0.f},{0.f,0.f,0.f,0.f}};
    float accl[4] = {0.f, 0.f, 0.f, 0.f};

    // First key tile with any nonzero mask: need min rel in tile < 32 + sp
    int jt0 = (int)floorf(((float)i0 - 95.f - sp) * (1.f / 64.f)) + 1;
    if (jt0 < 0) jt0 = 0;

    for (int jt = jt0; jt <= qt; jt++) {
        // load K (transposed) and V tiles
        {
            const float* ks = base + TC     + (size_t)(jt*64 + lr) * N3C + ld0;
            const float* vs = base + 2*TC   + (size_t)(jt*64 + lr) * N3C + ld0;
            #pragma unroll
            for (int i = 0; i < 16; i += 4) {
                float4 kv = *(const float4*)(ks + i);
                Kt[(ld0+i+0)*64 + lr] = kv.x;
                Kt[(ld0+i+1)*64 + lr] = kv.y;
                Kt[(ld0+i+2)*64 + lr] = kv.z;
                Kt[(ld0+i+3)*64 + lr] = kv.w;
                float4 vv = *(const float4*)(vs + i);
                *(float4*)(&Vs[lr*64 + ld0 + i]) = vv;
            }
        }
        __syncthreads();

        // S[k][q]: k = ty*4+ik, q = tx*4+iq
        float s[4][4] = {{0.f,0.f,0.f,0.f},{0.f,0.f,0.f,0.f},
                         {0.f,0.f,0.f,0.f},{0.f,0.f,0.f,0.f}};
        #pragma unroll 8
        for (int d = 0; d < 64; d++) {
            float4 a  = *(const float4*)(&Kt[d*64 + ty*4]);
            float4 bq = *(const float4*)(&Qt[d*64 + tx*4]);
            float ka[4] = {a.x, a.y, a.z, a.w};
            float qa[4] = {bq.x, bq.y, bq.z, bq.w};
            #pragma unroll
            for (int ik = 0; ik < 4; ik++)
                #pragma unroll
                for (int iq = 0; iq < 4; iq++)
                    s[ik][iq] = fmaf(ka[ik], qa[iq], s[ik][iq]);
        }

        // mask + exp, write Pt[k][q] (conflict-free float4 stores)
        #pragma unroll
        for (int ik = 0; ik < 4; ik++) {
            const int kglob = jt*64 + ty*4 + ik;
            float pr[4];
            #pragma unroll
            for (int iq = 0; iq < 4; iq++) {
                const int qglob = i0 + tx*4 + iq;
                const int rel = qglob - kglob;
                float p = 0.f;
                if (rel >= 0) {
                    float clipv = fminf(fmaxf((32.f + sp - (float)rel) * 0.03125f, 0.f), 1.f);
                    float mk = clipv * (sw0 + (((rel & 1) == 0) ? sw1 : 0.f));
                    p = __expf(s[ik][iq] * 0.125f) * mk;
                }
                pr[iq] = p;
                accl[iq] += p;
            }
            float4 pv = make_float4(pr[0], pr[1], pr[2], pr[3]);
            *(float4*)(&Pt[(ty*4 + ik)*64 + tx*4]) = pv;
        }
        __syncthreads();

        // Y[q][d] += P[q][k] V[k][d] ; q = ty*4+iq, d = tx*4+id
        #pragma unroll 8
        for (int kk = 0; kk < 64; kk++) {
            float4 a  = *(const float4*)(&Pt[kk*64 + ty*4]);
            float4 bv = *(const float4*)(&Vs[kk*64 + tx*4]);
            float pa[4] = {a.x, a.y, a.z, a.w};
            float va[4] = {bv.x, bv.y, bv.z, bv.w};
            #pragma unroll
            for (int iq = 0; iq < 4; iq++)
                #pragma unroll
                for (int id = 0; id < 4; id++)
                    accy[iq][id] = fmaf(pa[iq], va[id], accy[iq][id]);
        }
        __syncthreads();
    }

    // reduce row sums: accl is indexed by q = tx*4+iq
    #pragma unroll
    for (int iq = 0; iq < 4; iq++)
        atomicAdd(&lred[tx*4 + iq], accl[iq]);
    __syncthreads();

    // normalize and write out (q = ty*4+iq, d = tx*4+id), [b,t,C] layout
    #pragma unroll
    for (int iq = 0; iq < 4; iq++) {
        const float inv = 1.f / lred[ty*4 + iq];
        float4 o = make_float4(accy[iq][0]*inv, accy[iq][1]*inv,
                               accy[iq][2]*inv, accy[iq][3]*inv);
        *(float4*)(yatt + (size_t)(b*TT + i0 + ty*4 + iq) * TC + h*THD + tx*4) = o;
    }
}

// ---------------------------------------------------------------------------
// span_loss tail: 2e-6 * sum(sigmoid(span)*1024) / H
// ---------------------------------------------------------------------------
__global__ void tail_kernel(const float* __restrict__ span_params,
                            float* __restrict__ out, int out_size)
{
    if (threadIdx.x == 0 && blockIdx.x == 0) {
        float s = 0.f;
        for (int i = 0; i < TH; i++)
            s += 1024.f / (1.f + expf(-span_params[i]));
        if (out_size > MR * TC)
            out[MR * TC] = 2e-6f * s / 16.f;
    }
}

extern "C" void kernel_launch(void* const* d_in, const int* in_sizes, int n_in,
                              void* d_out, int out_size)
{
    const float* x    = (const float*)d_in[0];
    const float* Wqkv = (const float*)d_in[1];
    const float* Wpr  = (const float*)d_in[2];
    const float* span = (const float*)d_in[3];
    const float* strd = (const float*)d_in[4];
    float* out = (float*)d_out;

    float *qkv_ptr = nullptr, *yatt_ptr = nullptr;
    cudaGetSymbolAddress((void**)&qkv_ptr, g_qkv);
    cudaGetSymbolAddress((void**)&yatt_ptr, g_yatt);

    // 1) qkv = x @ Wqkv   (4096 x 3072 x 1024)
    sgemm128<<<dim3(N3C/128, MR/128), 256>>>(x, Wqkv, qkv_ptr, MR, N3C, TC);

    // 2) fused masked attention -> g_yatt in [b,t,C] layout
    const int smem_bytes = (16384 + 64) * (int)sizeof(float);
    cudaFuncSetAttribute(attn_kernel, cudaFuncAttributeMaxDynamicSharedMemorySize, smem_bytes);
    attn_kernel<<<dim3(TT/64, TH, TB), 256, smem_bytes>>>(qkv_ptr, span, strd, yatt_ptr);

    // 3) y = yatt @ Wproj (4096 x 1024 x 1024) -> d_out
    sgemm128<<<dim3(TC/128, MR/128), 256>>>(yatt_ptr, Wpr, out, MR, TC, TC);

    // 4) span_loss scalar
    tail_kernel<<<1, 32>>>(span, out, out_size);
}

// round 3
// speedup vs baseline: 1.4481x; 1.4481x over previous
#include <cuda_runtime.h>
#include <cuda_bf16.h>
#include <math.h>
#include <stdint.h>

#define TB 4
#define TT 1024
#define TC 1024
#define TH 16
#define THD 64
#define MR (TB*TT)          // 4096 rows
#define N3C (3*TC)          // 3072

// ---------------- scratch (allocation-free rule: device globals) -----------
static __device__ float g_qkv[(size_t)MR * N3C];     // 48 MB
static __device__ float g_yatt[(size_t)MR * TC];     // 16 MB
static __device__ __nv_bfloat16 g_xhi[(size_t)MR * TC];
static __device__ __nv_bfloat16 g_xlo[(size_t)MR * TC];
static __device__ __nv_bfloat16 g_wqkv_hi[(size_t)N3C * TC];   // W^T [3072,1024]
static __device__ __nv_bfloat16 g_wqkv_lo[(size_t)N3C * TC];
static __device__ __nv_bfloat16 g_wpr_hi[(size_t)TC * TC];     // W^T [1024,1024]
static __device__ __nv_bfloat16 g_wpr_lo[(size_t)TC * TC];
static __device__ __nv_bfloat16 g_yhi[(size_t)MR * TC];
static __device__ __nv_bfloat16 g_ylo[(size_t)MR * TC];

// ---------------- PTX helpers (baseline ISA, no arch-suffix features) ------
__device__ __forceinline__ uint32_t smem_u32(const void* p) {
    uint32_t a;
    asm("{ .reg .u64 t; cvta.to.shared.u64 t, %1; cvt.u32.u64 %0, t; }" : "=r"(a) : "l"(p));
    return a;
}
__device__ __forceinline__ void ldsm_x4(uint32_t (&r)[4], uint32_t addr) {
    asm volatile("ldmatrix.sync.aligned.m8n8.x4.shared.b16 {%0,%1,%2,%3}, [%4];"
        : "=r"(r[0]), "=r"(r[1]), "=r"(r[2]), "=r"(r[3]) : "r"(addr));
}
__device__ __forceinline__ void mma_bf16(float (&d)[4], const uint32_t (&a)[4],
                                         uint32_t b0, uint32_t b1) {
    asm volatile("mma.sync.aligned.m16n8k16.row.col.f32.bf16.bf16.f32 "
        "{%0,%1,%2,%3}, {%4,%5,%6,%7}, {%8,%9}, {%0,%1,%2,%3};"
        : "+f"(d[0]), "+f"(d[1]), "+f"(d[2]), "+f"(d[3])
        : "r"(a[0]), "r"(a[1]), "r"(a[2]), "r"(a[3]), "r"(b0), "r"(b1));
}

// ---------------------------------------------------------------------------
// Split-bf16 tensor-core GEMM: C[M,N](fp32) = (Ahi+Alo) @ (Bhi+Blo)^T
//   A row-major [M,K] bf16 hi/lo;  B given transposed [N,K] bf16 hi/lo.
// CTA 128x128, BK=32, 8 warps (4m x 2n), warp tile 32x64, mma.m16n8k16.
// 3 products: Ahi*Bhi + Ahi*Blo + Alo*Bhi  (lo*lo term ~2^-32, dropped).
// ---------------------------------------------------------------------------
__global__ __launch_bounds__(256) void gemm_mma(
    const __nv_bfloat16* __restrict__ Ahi, const __nv_bfloat16* __restrict__ Alo,
    const __nv_bfloat16* __restrict__ Bhi, const __nv_bfloat16* __restrict__ Blo,
    float* __restrict__ C, int M, int N, int K)
{
    __shared__ __nv_bfloat16 sAh[128][40];   // +8 pad: conflict-free LDSM
    __shared__ __nv_bfloat16 sAl[128][40];
    __shared__ __nv_bfloat16 sBh[128][40];
    __shared__ __nv_bfloat16 sBl[128][40];

    const int t = threadIdx.x, lane = t & 31, wid = t >> 5;
    const int wm = wid & 3, wn = wid >> 2;
    const int bm = blockIdx.y * 128, bn = blockIdx.x * 128;

    float acc[2][8][4];
    #pragma unroll
    for (int i = 0; i < 2; i++)
        #pragma unroll
        for (int j = 0; j < 8; j++)
            #pragma unroll
            for (int k = 0; k < 4; k++) acc[i][j][k] = 0.f;

    // per-thread staging coords: 512 16B-chunks per tile, 2 per thread
    const int c0 = t * 2;
    const int r0 = c0 >> 2, cc0 = (c0 & 3) * 8;
    const int r1 = (c0 + 1) >> 2, cc1 = ((c0 + 1) & 3) * 8;

    // LDSM lane addressing
    const int a_row = wm * 32 + (lane & 15);
    const int a_coff = (lane >> 4) * 8;
    const int b_row = wn * 64 + (lane & 7) + ((lane >> 4) & 1) * 8;
    const int b_coff = ((lane >> 3) & 1) * 8;

    for (int k0 = 0; k0 < K; k0 += 32) {
        *(uint4*)&sAh[r0][cc0] = *(const uint4*)(Ahi + (size_t)(bm + r0) * K + k0 + cc0);
        *(uint4*)&sAh[r1][cc1] = *(const uint4*)(Ahi + (size_t)(bm + r1) * K + k0 + cc1);
        *(uint4*)&sAl[r0][cc0] = *(const uint4*)(Alo + (size_t)(bm + r0) * K + k0 + cc0);
        *(uint4*)&sAl[r1][cc1] = *(const uint4*)(Alo + (size_t)(bm + r1) * K + k0 + cc1);
        *(uint4*)&sBh[r0][cc0] = *(const uint4*)(Bhi + (size_t)(bn + r0) * K + k0 + cc0);
        *(uint4*)&sBh[r1][cc1] = *(const uint4*)(Bhi + (size_t)(bn + r1) * K + k0 + cc1);
        *(uint4*)&sBl[r0][cc0] = *(const uint4*)(Blo + (size_t)(bn + r0) * K + k0 + cc0);
        *(uint4*)&sBl[r1][cc1] = *(const uint4*)(Blo + (size_t)(bn + r1) * K + k0 + cc1);
        __syncthreads();

        #pragma unroll
        for (int ks = 0; ks < 2; ks++) {
            uint32_t ah[2][4], al[2][4];
            #pragma unroll
            for (int mt = 0; mt < 2; mt++) {
                ldsm_x4(ah[mt], smem_u32(&sAh[a_row + mt*16][ks*16 + a_coff]));
                ldsm_x4(al[mt], smem_u32(&sAl[a_row + mt*16][ks*16 + a_coff]));
            }
            #pragma unroll
            for (int np = 0; np < 4; np++) {
                uint32_t bh[4], bl[4];
                ldsm_x4(bh, smem_u32(&sBh[b_row + np*16][ks*16 + b_coff]));
                ldsm_x4(bl, smem_u32(&sBl[b_row + np*16][ks*16 + b_coff]));
                #pragma unroll
                for (int half = 0; half < 2; half++) {
                    const int nt = np * 2 + half;
                    #pragma unroll
                    for (int mt = 0; mt < 2; mt++) {
                        mma_bf16(acc[mt][nt], ah[mt], bh[2*half], bh[2*half+1]);
                        mma_bf16(acc[mt][nt], ah[mt], bl[2*half], bl[2*half+1]);
                        mma_bf16(acc[mt][nt], al[mt], bh[2*half], bh[2*half+1]);
                    }
                }
            }
        }
        __syncthreads();
    }

    // epilogue: D frag lane l -> rows (g, g+8), cols (2t, 2t+1)
    const int g = lane >> 2, tq = lane & 3;
    #pragma unroll
    for (int mt = 0; mt < 2; mt++) {
        const int row = bm + wm*32 + mt*16 + g;
        #pragma unroll
        for (int nt = 0; nt < 8; nt++) {
            const int col = bn + wn*64 + nt*8 + 2*tq;
            *(float2*)(C + (size_t)row * N + col) =
                make_float2(acc[mt][nt][0], acc[mt][nt][1]);
            *(float2*)(C + (size_t)(row + 8) * N + col) =
                make_float2(acc[mt][nt][2], acc[mt][nt][3]);
        }
    }
}

// ---------------------------------------------------------------------------
// fp32 -> (hi, lo) bf16, elementwise. n4 = elems/4.
// ---------------------------------------------------------------------------
__global__ void convert_hilo(const float4* __restrict__ in,
                             __nv_bfloat162* __restrict__ hi,
                             __nv_bfloat162* __restrict__ lo, int n4)
{
    int i = blockIdx.x * blockDim.x + threadIdx.x;
    if (i >= n4) return;
    float4 v = in[i];
    __nv_bfloat16 h0 = __float2bfloat16(v.x), h1 = __float2bfloat16(v.y);
    __nv_bfloat16 h2 = __float2bfloat16(v.z), h3 = __float2bfloat16(v.w);
    __nv_bfloat16 l0 = __float2bfloat16(v.x - __bfloat162float(h0));
    __nv_bfloat16 l1 = __float2bfloat16(v.y - __bfloat162float(h1));
    __nv_bfloat16 l2 = __float2bfloat16(v.z - __bfloat162float(h2));
    __nv_bfloat16 l3 = __float2bfloat16(v.w - __bfloat162float(h3));
    hi[2*i]   = __halves2bfloat162(h0, h1);
    hi[2*i+1] = __halves2bfloat162(h2, h3);
    lo[2*i]   = __halves2bfloat162(l0, l1);
    lo[2*i+1] = __halves2bfloat162(l2, l3);
}

// ---------------------------------------------------------------------------
// W[K,N] fp32 -> T[N,K] (hi, lo) bf16 (transpose + split). block (32,8).
// ---------------------------------------------------------------------------
__global__ void transpose_hilo(const float* __restrict__ W,
                               __nv_bfloat16* __restrict__ Thi,
                               __nv_bfloat16* __restrict__ Tlo, int K, int N)
{
    __shared__ float tile[32][33];
    const int n0 = blockIdx.x * 32, k0 = blockIdx.y * 32;
    const int tx = threadIdx.x, ty = threadIdx.y;
    #pragma unroll
    for (int j = 0; j < 4; j++)
        tile[ty + 8*j][tx] = W[(size_t)(k0 + ty + 8*j) * N + n0 + tx];
    __syncthreads();
    #pragma unroll
    for (int j = 0; j < 4; j++) {
        float v = tile[tx][ty + 8*j];
        __nv_bfloat16 h = __float2bfloat16(v);
        size_t o = (size_t)(n0 + ty + 8*j) * K + k0 + tx;
        Thi[o] = h;
        Tlo[o] = __float2bfloat16(v - __bfloat162float(h));
    }
}

// ---------------------------------------------------------------------------
// Fused masked attention (fp32, ~peak FFMA) — unchanged from R1.
// ---------------------------------------------------------------------------
__global__ __launch_bounds__(256) void attn_kernel(const float* __restrict__ qkv,
                                                   const float* __restrict__ span_params,
                                                   const float* __restrict__ stride_params,
                                                   float* __restrict__ yatt)
{
    extern __shared__ float smf[];
    float* Qt   = smf;
    float* Kt   = smf + 4096;
    float* Vs   = smf + 8192;
    float* Pt   = smf + 12288;
    float* lred = smf + 16384;

    const int qt = blockIdx.x, h = blockIdx.y, b = blockIdx.z;
    const int t  = threadIdx.x;
    const int tx = t & 15, ty = t >> 4;
    const int i0 = qt * 64;

    const float sp = 1024.f / (1.f + __expf(-span_params[h]));
    const float p0 = stride_params[2*h], p1 = stride_params[2*h + 1];
    const float mxp = fmaxf(p0, p1);
    const float e0 = __expf(p0 - mxp), e1 = __expf(p1 - mxp);
    const float sw0 = e0 / (e0 + e1), sw1 = e1 / (e0 + e1);

    const float* base = qkv + (size_t)b * TT * N3C + h * THD;

    const int lr  = t >> 2;
    const int ld0 = (t & 3) << 4;

    {
        const float* src = base + (size_t)(i0 + lr) * N3C + ld0;
        #pragma unroll
        for (int i = 0; i < 16; i += 4) {
            float4 v = *(const float4*)(src + i);
            Qt[(ld0+i+0)*64 + lr] = v.x;
            Qt[(ld0+i+1)*64 + lr] = v.y;
            Qt[(ld0+i+2)*64 + lr] = v.z;
            Qt[(ld0+i+3)*64 + lr] = v.w;
        }
    }
    if (t < 64) lred[t] = 0.f;

    float accy[4][4] = {{0.f,0.f,0.f,0.f},{0.f,0.f,0.f,0.f},
                        {0.f,0.f,0.f,0.f},{0.f,0.f,0.f,0.f}};
    float accl[4] = {0.f, 0.f, 0.f, 0.f};

    int jt0 = (int)floorf(((float)i0 - 95.f - sp) * (1.f / 64.f)) + 1;
    if (jt0 < 0) jt0 = 0;

    for (int jt = jt0; jt <= qt; jt++) {
        {
            const float* ks = base + TC   + (size_t)(jt*64 + lr) * N3C + ld0;
            const float* vs = base + 2*TC + (size_t)(jt*64 + lr) * N3C + ld0;
            #pragma unroll
            for (int i = 0; i < 16; i += 4) {
                float4 kv = *(const float4*)(ks + i);
                Kt[(ld0+i+0)*64 + lr] = kv.x;
                Kt[(ld0+i+1)*64 + lr] = kv.y;
                Kt[(ld0+i+2)*64 + lr] = kv.z;
                Kt[(ld0+i+3)*64 + lr] = kv.w;
                float4 vv = *(const float4*)(vs + i);
                *(float4*)(&Vs[lr*64 + ld0 + i]) = vv;
            }
        }
        __syncthreads();

        float s[4][4] = {{0.f,0.f,0.f,0.f},{0.f,0.f,0.f,0.f},
                         {0.f,0.f,0.f,0.f},{0.f,0.f,0.f,0.f}};
        #pragma unroll 8
        for (int d = 0; d < 64; d++) {
            float4 a  = *(const float4*)(&Kt[d*64 + ty*4]);
            float4 bq = *(const float4*)(&Qt[d*64 + tx*4]);
            float ka[4] = {a.x, a.y, a.z, a.w};
            float qa[4] = {bq.x, bq.y, bq.z, bq.w};
            #pragma unroll
            for (int ik = 0; ik < 4; ik++)
                #pragma unroll
                for (int iq = 0; iq < 4; iq++)
                    s[ik][iq] = fmaf(ka[ik], qa[iq], s[ik][iq]);
        }

        #pragma unroll
        for (int ik = 0; ik < 4; ik++) {
            const int kglob = jt*64 + ty*4 + ik;
            float pr[4];
            #pragma unroll
            for (int iq = 0; iq < 4; iq++) {
                const int qglob = i0 + tx*4 + iq;
                const int rel = qglob - kglob;
                float p = 0.f;
                if (rel >= 0) {
                    float clipv = fminf(fmaxf((32.f + sp - (float)rel) * 0.03125f, 0.f), 1.f);
                    float mk = clipv * (sw0 + (((rel & 1) == 0) ? sw1 : 0.f));
                    p = __expf(s[ik][iq] * 0.125f) * mk;
                }
                pr[iq] = p;
                accl[iq] += p;
            }
            *(float4*)(&Pt[(ty*4 + ik)*64 + tx*4]) = make_float4(pr[0], pr[1], pr[2], pr[3]);
        }
        __syncthreads();

        #pragma unroll 8
        for (int kk = 0; kk < 64; kk++) {
            float4 a  = *(const float4*)(&Pt[kk*64 + ty*4]);
            float4 bv = *(const float4*)(&Vs[kk*64 + tx*4]);
            float pa[4] = {a.x, a.y, a.z, a.w};
            float va[4] = {bv.x, bv.y, bv.z, bv.w};
            #pragma unroll
            for (int iq = 0; iq < 4; iq++)
                #pragma unroll
                for (int id = 0; id < 4; id++)
                    accy[iq][id] = fmaf(pa[iq], va[id], accy[iq][id]);
        }
        __syncthreads();
    }

    #pragma unroll
    for (int iq = 0; iq < 4; iq++)
        atomicAdd(&lred[tx*4 + iq], accl[iq]);
    __syncthreads();

    #pragma unroll
    for (int iq = 0; iq < 4; iq++) {
        const float inv = 1.f / lred[ty*4 + iq];
        float4 o = make_float4(accy[iq][0]*inv, accy[iq][1]*inv,
                               accy[iq][2]*inv, accy[iq][3]*inv);
        *(float4*)(yatt + (size_t)(b*TT + i0 + ty*4 + iq) * TC + h*THD + tx*4) = o;
    }
}

// ---------------------------------------------------------------------------
__global__ void tail_kernel(const float* __restrict__ span_params,
                            float* __restrict__ out, int out_size)
{
    if (threadIdx.x == 0 && blockIdx.x == 0) {
        float s = 0.f;
        for (int i = 0; i < TH; i++)
            s += 1024.f / (1.f + expf(-span_params[i]));
        if (out_size > MR * TC)
            out[MR * TC] = 2e-6f * s / 16.f;
    }
}

extern "C" void kernel_launch(void* const* d_in, const int* in_sizes, int n_in,
                              void* d_out, int out_size)
{
    const float* x    = (const float*)d_in[0];
    const float* Wqkv = (const float*)d_in[1];
    const float* Wpr  = (const float*)d_in[2];
    const float* span = (const float*)d_in[3];
    const float* strd = (const float*)d_in[4];
    float* out = (float*)d_out;

    float *qkv_p, *yatt_p;
    __nv_bfloat16 *xhi, *xlo, *wqh, *wql, *wph, *wpl, *yhi, *ylo;
    cudaGetSymbolAddress((void**)&qkv_p, g_qkv);
    cudaGetSymbolAddress((void**)&yatt_p, g_yatt);
    cudaGetSymbolAddress((void**)&xhi, g_xhi);
    cudaGetSymbolAddress((void**)&xlo, g_xlo);
    cudaGetSymbolAddress((void**)&wqh, g_wqkv_hi);
    cudaGetSymbolAddress((void**)&wql, g_wqkv_lo);
    cudaGetSymbolAddress((void**)&wph, g_wpr_hi);
    cudaGetSymbolAddress((void**)&wpl, g_wpr_lo);
    cudaGetSymbolAddress((void**)&yhi, g_yhi);
    cudaGetSymbolAddress((void**)&ylo, g_ylo);

    static bool attr_set = false;
    const int attn_smem = (16384 + 64) * (int)sizeof(float);
    if (!attr_set) {
        cudaFuncSetAttribute(attn_kernel, cudaFuncAttributeMaxDynamicSharedMemorySize, attn_smem);
        attr_set = true;
    }

    // 0) operand prep: x -> hi/lo bf16 ; W -> transposed hi/lo bf16
    convert_hilo<<<(MR*TC/4 + 255)/256, 256>>>((const float4*)x,
        (__nv_bfloat162*)xhi, (__nv_bfloat162*)xlo, MR*TC/4);
    transpose_hilo<<<dim3(N3C/32, TC/32), dim3(32, 8)>>>(Wqkv, wqh, wql, TC, N3C);
    transpose_hilo<<<dim3(TC/32, TC/32), dim3(32, 8)>>>(Wpr, wph, wpl, TC, TC);

    // 1) qkv = x @ Wqkv  (split-bf16 mma.sync)
    gemm_mma<<<dim3(N3C/128, MR/128), 256>>>(xhi, xlo, wqh, wql, qkv_p, MR, N3C, TC);

    // 2) fused masked attention -> g_yatt [b,t,C]
    attn_kernel<<<dim3(TT/64, TH, TB), 256, attn_smem>>>(qkv_p, span, strd, yatt_p);

    // 3) y = yatt @ Wproj (split-bf16 mma.sync) -> d_out
    convert_hilo<<<(MR*TC/4 + 255)/256, 256>>>((const float4*)yatt_p,
        (__nv_bfloat162*)yhi, (__nv_bfloat162*)ylo, MR*TC/4);
    gemm_mma<<<dim3(TC/128, MR/128), 256>>>(yhi, ylo, wph, wpl, out, MR, TC, TC);

    // 4) span_loss scalar
    tail_kernel<<<1, 32>>>(span, out, out_size);
}

// round 4
// speedup vs baseline: 1.7454x; 1.2053x over previous
#include <cuda_runtime.h>
#include <cuda_bf16.h>
#include <math.h>
#include <stdint.h>

#define TB 4
#define TT 1024
#define TC 1024
#define TH 16
#define THD 64
#define MR (TB*TT)          // 4096 rows
#define N3C (3*TC)          // 3072

// ---------------- scratch (allocation-free rule: device globals) -----------
static __device__ float g_qkv[(size_t)MR * N3C];     // 48 MB
static __device__ float g_yatt[(size_t)MR * TC];     // 16 MB
static __device__ __nv_bfloat16 g_xhi[(size_t)MR * TC];
static __device__ __nv_bfloat16 g_xlo[(size_t)MR * TC];
static __device__ __nv_bfloat16 g_wqkv_hi[(size_t)N3C * TC];   // W^T [3072,1024]
static __device__ __nv_bfloat16 g_wqkv_lo[(size_t)N3C * TC];
static __device__ __nv_bfloat16 g_wpr_hi[(size_t)TC * TC];     // W^T [1024,1024]
static __device__ __nv_bfloat16 g_wpr_lo[(size_t)TC * TC];
static __device__ __nv_bfloat16 g_yhi[(size_t)MR * TC];
static __device__ __nv_bfloat16 g_ylo[(size_t)MR * TC];

// ---------------- PTX helpers (baseline ISA only) ---------------------------
__device__ __forceinline__ uint32_t smem_u32(const void* p) {
    uint32_t a;
    asm("{ .reg .u64 t; cvta.to.shared.u64 t, %1; cvt.u32.u64 %0, t; }" : "=r"(a) : "l"(p));
    return a;
}
__device__ __forceinline__ void ldsm_x4(uint32_t (&r)[4], uint32_t addr) {
    asm volatile("ldmatrix.sync.aligned.m8n8.x4.shared.b16 {%0,%1,%2,%3}, [%4];"
        : "=r"(r[0]), "=r"(r[1]), "=r"(r[2]), "=r"(r[3]) : "r"(addr));
}
__device__ __forceinline__ void mma_bf16(float (&d)[4], const uint32_t (&a)[4],
                                         uint32_t b0, uint32_t b1) {
    asm volatile("mma.sync.aligned.m16n8k16.row.col.f32.bf16.bf16.f32 "
        "{%0,%1,%2,%3}, {%4,%5,%6,%7}, {%8,%9}, {%0,%1,%2,%3};"
        : "+f"(d[0]), "+f"(d[1]), "+f"(d[2]), "+f"(d[3])
        : "r"(a[0]), "r"(a[1]), "r"(a[2]), "r"(a[3]), "r"(b0), "r"(b1));
}
__device__ __forceinline__ void cp_async16(uint32_t dst, const void* src) {
    asm volatile("cp.async.cg.shared.global [%0], [%1], 16;" :: "r"(dst), "l"(src) : "memory");
}
#define CP_COMMIT() asm volatile("cp.async.commit_group;" ::: "memory")
#define CP_WAIT1()  asm volatile("cp.async.wait_group 1;" ::: "memory")
#define CP_WAIT0()  asm volatile("cp.async.wait_group 0;" ::: "memory")

// smem tile geometry: 128 rows x 40 bf16 (pad 8 -> conflict-free LDSM)
#define TROW 40
#define TILE_ELEMS (128*TROW)           // 5120 bf16
#define STAGE_ELEMS (4*TILE_ELEMS)      // Ah,Al,Bh,Bl
#define GEMM_SMEM (2*STAGE_ELEMS*2)     // bytes (2 stages, bf16)

// ---------------------------------------------------------------------------
// Split-bf16 tensor-core GEMM with cp.async 2-stage pipeline:
//   C[M,N](fp32) = (Ahi+Alo) @ (Bhi+Blo)^T ; 3 products (lo*lo dropped).
// CTA 128x128, BK=32, 8 warps (4m x 2n), warp tile 32x64, mma.m16n8k16.
// ---------------------------------------------------------------------------
__global__ __launch_bounds__(256) void gemm_mma(
    const __nv_bfloat16* __restrict__ Ahi, const __nv_bfloat16* __restrict__ Alo,
    const __nv_bfloat16* __restrict__ Bhi, const __nv_bfloat16* __restrict__ Blo,
    float* __restrict__ C, int M, int N, int K)
{
    extern __shared__ __nv_bfloat16 smem[];   // 2 stages x 4 tiles

    const int t = threadIdx.x, lane = t & 31, wid = t >> 5;
    const int wm = wid & 3, wn = wid >> 2;
    const int bm = blockIdx.y * 128, bn = blockIdx.x * 128;

    float acc[2][8][4];
    #pragma unroll
    for (int i = 0; i < 2; i++)
        #pragma unroll
        for (int j = 0; j < 8; j++)
            #pragma unroll
            for (int k = 0; k < 4; k++) acc[i][j][k] = 0.f;

    // staging coords: 512 16B chunks per tile, 2 per thread
    const int c0 = t * 2;
    const int r0 = c0 >> 2,       cc0 = (c0 & 3) * 8;
    const int r1 = (c0 + 1) >> 2, cc1 = ((c0 + 1) & 3) * 8;

    const __nv_bfloat16* gsrc[4] = { Ahi, Alo, Bhi, Blo };
    const size_t grow0[4] = { (size_t)(bm + r0), (size_t)(bm + r0),
                              (size_t)(bn + r0), (size_t)(bn + r0) };
    const size_t grow1[4] = { (size_t)(bm + r1), (size_t)(bm + r1),
                              (size_t)(bn + r1), (size_t)(bn + r1) };
    uint32_t sdst0[4], sdst1[4];
    #pragma unroll
    for (int w = 0; w < 4; w++) {
        sdst0[w] = smem_u32(smem + w * TILE_ELEMS + r0 * TROW + cc0);
        sdst1[w] = smem_u32(smem + w * TILE_ELEMS + r1 * TROW + cc1);
    }
    const uint32_t stage_bytes = STAGE_ELEMS * 2;

    // LDSM lane addressing
    const int a_row = wm * 32 + (lane & 15);
    const int a_coff = (lane >> 4) * 8;
    const int b_row = wn * 64 + (lane & 7) + ((lane >> 4) & 1) * 8;
    const int b_coff = ((lane >> 3) & 1) * 8;

    const int niter = K >> 5;   // K/32

    // prologue: issue stage 0
    #pragma unroll
    for (int w = 0; w < 4; w++) {
        cp_async16(sdst0[w], gsrc[w] + grow0[w] * K + cc0);
        cp_async16(sdst1[w], gsrc[w] + grow1[w] * K + cc1);
    }
    CP_COMMIT();

    for (int it = 0; it < niter; it++) {
        // issue next stage
        if (it + 1 < niter) {
            const int kn = (it + 1) << 5;
            const uint32_t soff = ((it + 1) & 1) * stage_bytes;
            #pragma unroll
            for (int w = 0; w < 4; w++) {
                cp_async16(sdst0[w] + soff, gsrc[w] + grow0[w] * K + kn + cc0);
                cp_async16(sdst1[w] + soff, gsrc[w] + grow1[w] * K + kn + cc1);
            }
            CP_COMMIT();
            CP_WAIT1();
        } else {
            CP_WAIT0();
        }
        __syncthreads();

        const __nv_bfloat16* bs = smem + (it & 1) * STAGE_ELEMS;
        #pragma unroll
        for (int ks = 0; ks < 2; ks++) {
            uint32_t ah[2][4], al[2][4];
            #pragma unroll
            for (int mt = 0; mt < 2; mt++) {
                ldsm_x4(ah[mt], smem_u32(bs + (a_row + mt*16) * TROW + ks*16 + a_coff));
                ldsm_x4(al[mt], smem_u32(bs + TILE_ELEMS + (a_row + mt*16) * TROW + ks*16 + a_coff));
            }
            #pragma unroll
            for (int np = 0; np < 4; np++) {
                uint32_t bh[4], bl[4];
                ldsm_x4(bh, smem_u32(bs + 2*TILE_ELEMS + (b_row + np*16) * TROW + ks*16 + b_coff));
                ldsm_x4(bl, smem_u32(bs + 3*TILE_ELEMS + (b_row + np*16) * TROW + ks*16 + b_coff));
                #pragma unroll
                for (int half = 0; half < 2; half++) {
                    const int nt = np * 2 + half;
                    #pragma unroll
                    for (int mt = 0; mt < 2; mt++) {
                        mma_bf16(acc[mt][nt], ah[mt], bh[2*half], bh[2*half+1]);
                        mma_bf16(acc[mt][nt], ah[mt], bl[2*half], bl[2*half+1]);
                        mma_bf16(acc[mt][nt], al[mt], bh[2*half], bh[2*half+1]);
                    }
                }
            }
        }
        __syncthreads();
    }

    // epilogue: D frag lane l -> rows (g, g+8), cols (2t, 2t+1)
    const int g = lane >> 2, tq = lane & 3;
    #pragma unroll
    for (int mt = 0; mt < 2; mt++) {
        const int row = bm + wm*32 + mt*16 + g;
        #pragma unroll
        for (int nt = 0; nt < 8; nt++) {
            const int col = bn + wn*64 + nt*8 + 2*tq;
            *(float2*)(C + (size_t)row * N + col) =
                make_float2(acc[mt][nt][0], acc[mt][nt][1]);
            *(float2*)(C + (size_t)(row + 8) * N + col) =
                make_float2(acc[mt][nt][2], acc[mt][nt][3]);
        }
    }
}

// ---------------------------------------------------------------------------
// fp32 -> (hi, lo) bf16, elementwise. n4 = elems/4.
// ---------------------------------------------------------------------------
__global__ void convert_hilo(const float4* __restrict__ in,
                             __nv_bfloat162* __restrict__ hi,
                             __nv_bfloat162* __restrict__ lo, int n4)
{
    int i = blockIdx.x * blockDim.x + threadIdx.x;
    if (i >= n4) return;
    float4 v = in[i];
    __nv_bfloat16 h0 = __float2bfloat16(v.x), h1 = __float2bfloat16(v.y);
    __nv_bfloat16 h2 = __float2bfloat16(v.z), h3 = __float2bfloat16(v.w);
    __nv_bfloat16 l0 = __float2bfloat16(v.x - __bfloat162float(h0));
    __nv_bfloat16 l1 = __float2bfloat16(v.y - __bfloat162float(h1));
    __nv_bfloat16 l2 = __float2bfloat16(v.z - __bfloat162float(h2));
    __nv_bfloat16 l3 = __float2bfloat16(v.w - __bfloat162float(h3));
    hi[2*i]   = __halves2bfloat162(h0, h1);
    hi[2*i+1] = __halves2bfloat162(h2, h3);
    lo[2*i]   = __halves2bfloat162(l0, l1);
    lo[2*i+1] = __halves2bfloat162(l2, l3);
}

// ---------------------------------------------------------------------------
// W[K,N] fp32 -> T[N,K] (hi, lo) bf16 (transpose + split). block (32,8).
// ---------------------------------------------------------------------------
__global__ void transpose_hilo(const float* __restrict__ W,
                               __nv_bfloat16* __restrict__ Thi,
                               __nv_bfloat16* __restrict__ Tlo, int K, int N)
{
    __shared__ float tile[32][33];
    const int n0 = blockIdx.x * 32, k0 = blockIdx.y * 32;
    const int tx = threadIdx.x, ty = threadIdx.y;
    #pragma unroll
    for (int j = 0; j < 4; j++)
        tile[ty + 8*j][tx] = W[(size_t)(k0 + ty + 8*j) * N + n0 + tx];
    __syncthreads();
    #pragma unroll
    for (int j = 0; j < 4; j++) {
        float v = tile[tx][ty + 8*j];
        __nv_bfloat16 h = __float2bfloat16(v);
        size_t o = (size_t)(n0 + ty + 8*j) * K + k0 + tx;
        Thi[o] = h;
        Tlo[o] = __float2bfloat16(v - __bfloat162float(h));
    }
}

// ---------------------------------------------------------------------------
// Fused masked attention (fp32, ~peak FFMA) — unchanged.
// ---------------------------------------------------------------------------
__global__ __launch_bounds__(256) void attn_kernel(const float* __restrict__ qkv,
                                                   const float* __restrict__ span_params,
                                                   const float* __restrict__ stride_params,
                                                   float* __restrict__ yatt)
{
    extern __shared__ float smf[];
    float* Qt   = smf;
    float* Kt   = smf + 4096;
    float* Vs   = smf + 8192;
    float* Pt   = smf + 12288;
    float* lred = smf + 16384;

    const int qt = blockIdx.x, h = blockIdx.y, b = blockIdx.z;
    const int t  = threadIdx.x;
    const int tx = t & 15, ty = t >> 4;
    const int i0 = qt * 64;

    const float sp = 1024.f / (1.f + __expf(-span_params[h]));
    const float p0 = stride_params[2*h], p1 = stride_params[2*h + 1];
    const float mxp = fmaxf(p0, p1);
    const float e0 = __expf(p0 - mxp), e1 = __expf(p1 - mxp);
    const float sw0 = e0 / (e0 + e1), sw1 = e1 / (e0 + e1);

    const float* base = qkv + (size_t)b * TT * N3C + h * THD;

    const int lr  = t >> 2;
    const int ld0 = (t & 3) << 4;

    {
        const float* src = base + (size_t)(i0 + lr) * N3C + ld0;
        #pragma unroll
        for (int i = 0; i < 16; i += 4) {
            float4 v = *(const float4*)(src + i);
            Qt[(ld0+i+0)*64 + lr] = v.x;
            Qt[(ld0+i+1)*64 + lr] = v.y;
            Qt[(ld0+i+2)*64 + lr] = v.z;
            Qt[(ld0+i+3)*64 + lr] = v.w;
        }
    }
    if (t < 64) lred[t] = 0.f;

    float accy[4][4] = {{0.f,0.f,0.f,0.f},{0.f,0.f,0.f,0.f},
                        {0.f,0.f,0.f,0.f},{0.f,0.f,0.f,0.f}};
    float accl[4] = {0.f, 0.f, 0.f, 0.f};

    int jt0 = (int)floorf(((float)i0 - 95.f - sp) * (1.f / 64.f)) + 1;
    if (jt0 < 0) jt0 = 0;

    for (int jt = jt0; jt <= qt; jt++) {
        {
            const float* ks = base + TC   + (size_t)(jt*64 + lr) * N3C + ld0;
            const float* vs = base + 2*TC + (size_t)(jt*64 + lr) * N3C + ld0;
            #pragma unroll
            for (int i = 0; i < 16; i += 4) {
                float4 kv = *(const float4*)(ks + i);
                Kt[(ld0+i+0)*64 + lr] = kv.x;
                Kt[(ld0+i+1)*64 + lr] = kv.y;
                Kt[(ld0+i+2)*64 + lr] = kv.z;
                Kt[(ld0+i+3)*64 + lr] = kv.w;
                float4 vv = *(const float4*)(vs + i);
                *(float4*)(&Vs[lr*64 + ld0 + i]) = vv;
            }
        }
        __syncthreads();

        float s[4][4] = {{0.f,0.f,0.f,0.f},{0.f,0.f,0.f,0.f},
                         {0.f,0.f,0.f,0.f},{0.f,0.f,0.f,0.f}};
        #pragma unroll 8
        for (int d = 0; d < 64; d++) {
            float4 a  = *(const float4*)(&Kt[d*64 + ty*4]);
            float4 bq = *(const float4*)(&Qt[d*64 + tx*4]);
            float ka[4] = {a.x, a.y, a.z, a.w};
            float qa[4] = {bq.x, bq.y, bq.z, bq.w};
            #pragma unroll
            for (int ik = 0; ik < 4; ik++)
                #pragma unroll
                for (int iq = 0; iq < 4; iq++)
                    s[ik][iq] = fmaf(ka[ik], qa[iq], s[ik][iq]);
        }

        #pragma unroll
        for (int ik = 0; ik < 4; ik++) {
            const int kglob = jt*64 + ty*4 + ik;
            float pr[4];
            #pragma unroll
            for (int iq = 0; iq < 4; iq++) {
                const int qglob = i0 + tx*4 + iq;
                const int rel = qglob - kglob;
                float p = 0.f;
                if (rel >= 0) {
                    float clipv = fminf(fmaxf((32.f + sp - (float)rel) * 0.03125f, 0.f), 1.f);
                    float mk = clipv * (sw0 + (((rel & 1) == 0) ? sw1 : 0.f));
                    p = __expf(s[ik][iq] * 0.125f) * mk;
                }
                pr[iq] = p;
                accl[iq] += p;
            }
            *(float4*)(&Pt[(ty*4 + ik)*64 + tx*4]) = make_float4(pr[0], pr[1], pr[2], pr[3]);
        }
        __syncthreads();

        #pragma unroll 8
        for (int kk = 0; kk < 64; kk++) {
            float4 a  = *(const float4*)(&Pt[kk*64 + ty*4]);
            float4 bv = *(const float4*)(&Vs[kk*64 + tx*4]);
            float pa[4] = {a.x, a.y, a.z, a.w};
            float va[4] = {bv.x, bv.y, bv.z, bv.w};
            #pragma unroll
            for (int iq = 0; iq < 4; iq++)
                #pragma unroll
                for (int id = 0; id < 4; id++)
                    accy[iq][id] = fmaf(pa[iq], va[id], accy[iq][id]);
        }
        __syncthreads();
    }

    #pragma unroll
    for (int iq = 0; iq < 4; iq++)
        atomicAdd(&lred[tx*4 + iq], accl[iq]);
    __syncthreads();

    #pragma unroll
    for (int iq = 0; iq < 4; iq++) {
        const float inv = 1.f / lred[ty*4 + iq];
        float4 o = make_float4(accy[iq][0]*inv, accy[iq][1]*inv,
                               accy[iq][2]*inv, accy[iq][3]*inv);
        *(float4*)(yatt + (size_t)(b*TT + i0 + ty*4 + iq) * TC + h*THD + tx*4) = o;
    }
}

// ---------------------------------------------------------------------------
__global__ void tail_kernel(const float* __restrict__ span_params,
                            float* __restrict__ out, int out_size)
{
    if (threadIdx.x == 0 && blockIdx.x == 0) {
        float s = 0.f;
        for (int i = 0; i < TH; i++)
            s += 1024.f / (1.f + expf(-span_params[i]));
        if (out_size > MR * TC)
            out[MR * TC] = 2e-6f * s / 16.f;
    }
}

extern "C" void kernel_launch(void* const* d_in, const int* in_sizes, int n_in,
                              void* d_out, int out_size)
{
    const float* x    = (const float*)d_in[0];
    const float* Wqkv = (const float*)d_in[1];
    const float* Wpr  = (const float*)d_in[2];
    const float* span = (const float*)d_in[3];
    const float* strd = (const float*)d_in[4];
    float* out = (float*)d_out;

    float *qkv_p, *yatt_p;
    __nv_bfloat16 *xhi, *xlo, *wqh, *wql, *wph, *wpl, *yhi, *ylo;
    cudaGetSymbolAddress((void**)&qkv_p, g_qkv);
    cudaGetSymbolAddress((void**)&yatt_p, g_yatt);
    cudaGetSymbolAddress((void**)&xhi, g_xhi);
    cudaGetSymbolAddress((void**)&xlo, g_xlo);
    cudaGetSymbolAddress((void**)&wqh, g_wqkv_hi);
    cudaGetSymbolAddress((void**)&wql, g_wqkv_lo);
    cudaGetSymbolAddress((void**)&wph, g_wpr_hi);
    cudaGetSymbolAddress((void**)&wpl, g_wpr_lo);
    cudaGetSymbolAddress((void**)&yhi, g_yhi);
    cudaGetSymbolAddress((void**)&ylo, g_ylo);

    static bool attr_set = false;
    const int attn_smem = (16384 + 64) * (int)sizeof(float);
    if (!attr_set) {
        cudaFuncSetAttribute(gemm_mma, cudaFuncAttributeMaxDynamicSharedMemorySize, GEMM_SMEM);
        cudaFuncSetAttribute(attn_kernel, cudaFuncAttributeMaxDynamicSharedMemorySize, attn_smem);
        attr_set = true;
    }

    // 0) operand prep: x -> hi/lo bf16 ; W -> transposed hi/lo bf16
    convert_hilo<<<(MR*TC/4 + 255)/256, 256>>>((const float4*)x,
        (__nv_bfloat162*)xhi, (__nv_bfloat162*)xlo, MR*TC/4);
    transpose_hilo<<<dim3(N3C/32, TC/32), dim3(32, 8)>>>(Wqkv, wqh, wql, TC, N3C);
    transpose_hilo<<<dim3(TC/32, TC/32), dim3(32, 8)>>>(Wpr, wph, wpl, TC, TC);

    // 1) qkv = x @ Wqkv  (split-bf16 mma.sync, cp.async pipelined)
    gemm_mma<<<dim3(N3C/128, MR/128), 256, GEMM_SMEM>>>(xhi, xlo, wqh, wql,
                                                        qkv_p, MR, N3C, TC);

    // 2) fused masked attention -> g_yatt [b,t,C]
    attn_kernel<<<dim3(TT/64, TH, TB), 256, attn_smem>>>(qkv_p, span, strd, yatt_p);

    // 3) y = yatt @ Wproj -> d_out
    convert_hilo<<<(MR*TC/4 + 255)/256, 256>>>((const float4*)yatt_p,
        (__nv_bfloat162*)yhi, (__nv_bfloat162*)ylo, MR*TC/4);
    gemm_mma<<<dim3(TC/128, MR/128), 256, GEMM_SMEM>>>(yhi, ylo, wph, wpl,
                                                       out, MR, TC, TC);

    // 4) span_loss scalar
    tail_kernel<<<1, 32>>>(span, out, out_size);
}